// round 10
// baseline (speedup 1.0000x reference)
#include <cuda_runtime.h>
#include <cuda_bf16.h>
#include <cstdint>

#define NN 100000
#define EE 1250000
#define DD 64
#define NB ((NN + 255) / 256)   // 391 scan blocks

// ---------------------------------------------------------------------------
// Scratch (__device__ globals; zero-initialized at load; self-restoring)
// ---------------------------------------------------------------------------
__device__ int   g_cnt[NN];                // edge count per dst (cleared by scan1)
__device__ float g_deg[NN];                // weighted degree (cleared by scan1)
__device__ float g_dis[NN];                // deg^{-1/2}
__device__ int   g_rowptr[NN];             // local-exclusive after scan1; local-inclusive after reorder
__device__ int   g_bsum[NB];               // block totals (scan1)
__device__ int   g_bsumx[NB];              // exclusive block offsets (scan2)
__device__ int2  g_epair[EE];              // (src, coef-bits), dst-grouped
__device__ float g_h[NN * DD];             // gemm output buffer
__device__ float g_agg[NN * DD];           // gather output buffer

// ---------------------------------------------------------------------------
// Histogram: int count + float weighted degree, 4 edges/thread.
// ---------------------------------------------------------------------------
__global__ void k_hist(const int* __restrict__ dst, const float* __restrict__ w) {
    int t = blockIdx.x * blockDim.x + threadIdx.x;
    int e = t * 4;
    if (e + 4 <= EE) {
        int4 d = *reinterpret_cast<const int4*>(dst + e);
        float4 wv = *reinterpret_cast<const float4*>(w + e);
        atomicAdd(&g_cnt[d.x], 1);
        atomicAdd(&g_cnt[d.y], 1);
        atomicAdd(&g_cnt[d.z], 1);
        atomicAdd(&g_cnt[d.w], 1);
        atomicAdd(&g_deg[d.x], wv.x);
        atomicAdd(&g_deg[d.y], wv.y);
        atomicAdd(&g_deg[d.z], wv.z);
        atomicAdd(&g_deg[d.w], wv.w);
    } else {
        for (; e < EE; e++) {
            atomicAdd(&g_cnt[dst[e]], 1);
            atomicAdd(&g_deg[dst[e]], w[e]);
        }
    }
}

// ---------------------------------------------------------------------------
// scan1: read+clear cnt/deg, compute dis, block-local exclusive scan.
// ---------------------------------------------------------------------------
__global__ void k_scan1() {
    __shared__ int sh[256];
    int t = threadIdx.x;
    int i = blockIdx.x * 256 + t;
    int cnt = 0;
    if (i < NN) {
        cnt = g_cnt[i];
        g_cnt[i] = 0;                                  // restore for next run
        float deg = g_deg[i];
        g_deg[i] = 0.0f;                               // restore for next run
        g_dis[i] = rsqrtf(deg + 1.0f);
    }
    sh[t] = cnt;
    __syncthreads();
    for (int off = 1; off < 256; off <<= 1) {
        int u = (t >= off) ? sh[t - off] : 0;
        __syncthreads();
        sh[t] += u;
        __syncthreads();
    }
    if (i < NN) g_rowptr[i] = sh[t] - cnt;             // local exclusive
    if (t == 255) g_bsum[blockIdx.x] = sh[255];
}

// scan2: exclusive scan of 391 block totals -> g_bsumx
__global__ void k_scan2() {
    __shared__ int sh[512];
    int t = threadIdx.x;
    int v = (t < NB) ? g_bsum[t] : 0;
    sh[t] = v;
    __syncthreads();
    for (int off = 1; off < 512; off <<= 1) {
        int u = (t >= off) ? sh[t - off] : 0;
        __syncthreads();
        sh[t] += u;
        __syncthreads();
    }
    if (t < NB) g_bsumx[t] = sh[t] - v;
}

// ---------------------------------------------------------------------------
// 64-row GEMM body (device function): H[row0..row0+64) = X @ W^T
// 256 threads: lane = row within 32-group, grp = 8-col group. 2x8 outputs.
// ---------------------------------------------------------------------------
__device__ __forceinline__ void gemm_body(const float* __restrict__ X,
                                          const float* __restrict__ W,
                                          float* __restrict__ H,
                                          int row0,
                                          float (*Xs)[68], float (*Ws)[DD]) {
    int tid = threadIdx.x;
    int lane = tid & 31;
    int grp  = tid >> 5;

    for (int idx = tid; idx < (DD * DD) / 4; idx += 256) {
        int o = idx >> 4;
        int k4 = (idx & 15) * 4;
        float4 v = *reinterpret_cast<const float4*>(W + o * DD + k4);
        Ws[k4 + 0][o] = v.x;
        Ws[k4 + 1][o] = v.y;
        Ws[k4 + 2][o] = v.z;
        Ws[k4 + 3][o] = v.w;
    }
    for (int idx = tid; idx < (64 * DD) / 4; idx += 256) {
        int r = idx >> 4;
        int k4 = (idx & 15) * 4;
        int row = row0 + r;
        float4 v = (row < NN) ? *reinterpret_cast<const float4*>(X + (size_t)row * DD + k4)
                              : make_float4(0.f, 0.f, 0.f, 0.f);
        *reinterpret_cast<float4*>(&Xs[r][k4]) = v;
    }
    __syncthreads();

    int c0 = grp * 8;
    float acc[2][8];
#pragma unroll
    for (int i = 0; i < 2; i++)
#pragma unroll
        for (int j = 0; j < 8; j++) acc[i][j] = 0.0f;

#pragma unroll 4
    for (int k = 0; k < DD; k++) {
        float xv0 = Xs[lane     ][k];
        float xv1 = Xs[lane + 32][k];
        float4 w0 = *reinterpret_cast<const float4*>(&Ws[k][c0]);
        float4 w1 = *reinterpret_cast<const float4*>(&Ws[k][c0 + 4]);
        float wv[8] = {w0.x, w0.y, w0.z, w0.w, w1.x, w1.y, w1.z, w1.w};
#pragma unroll
        for (int j = 0; j < 8; j++) {
            acc[0][j] = fmaf(xv0, wv[j], acc[0][j]);
            acc[1][j] = fmaf(xv1, wv[j], acc[1][j]);
        }
    }

#pragma unroll
    for (int i = 0; i < 2; i++) {
        int row = row0 + lane + i * 32;
        if (row < NN) {
            float* hp = H + (size_t)row * DD + c0;
            *reinterpret_cast<float4*>(hp)     = make_float4(acc[i][0], acc[i][1], acc[i][2], acc[i][3]);
            *reinterpret_cast<float4*>(hp + 4) = make_float4(acc[i][4], acc[i][5], acc[i][6], acc[i][7]);
        }
    }
}

// ---------------------------------------------------------------------------
// Reorder body: place (src, coef-bits), coef = dis[s]*w*dis[d]. 4 edges/thread.
// ---------------------------------------------------------------------------
__device__ __forceinline__ void reorder_body(const int* __restrict__ src,
                                             const int* __restrict__ dst,
                                             const float* __restrict__ w,
                                             int bid) {
    int t = bid * 256 + threadIdx.x;
    int e = t * 4;
    if (e + 4 <= EE) {
        int4 s = *reinterpret_cast<const int4*>(src + e);
        int4 d = *reinterpret_cast<const int4*>(dst + e);
        float4 wv = *reinterpret_cast<const float4*>(w + e);
        float c0 = g_dis[s.x] * wv.x * g_dis[d.x];
        float c1 = g_dis[s.y] * wv.y * g_dis[d.y];
        float c2 = g_dis[s.z] * wv.z * g_dis[d.z];
        float c3 = g_dis[s.w] * wv.w * g_dis[d.w];
        int p0 = g_bsumx[d.x >> 8] + atomicAdd(&g_rowptr[d.x], 1);
        int p1 = g_bsumx[d.y >> 8] + atomicAdd(&g_rowptr[d.y], 1);
        int p2 = g_bsumx[d.z >> 8] + atomicAdd(&g_rowptr[d.z], 1);
        int p3 = g_bsumx[d.w >> 8] + atomicAdd(&g_rowptr[d.w], 1);
        g_epair[p0] = make_int2(s.x, __float_as_int(c0));
        g_epair[p1] = make_int2(s.y, __float_as_int(c1));
        g_epair[p2] = make_int2(s.z, __float_as_int(c2));
        g_epair[p3] = make_int2(s.w, __float_as_int(c3));
    } else {
        for (; e < EE; e++) {
            int sv = src[e];
            int d = dst[e];
            float c = g_dis[sv] * w[e] * g_dis[d];
            int pos = g_bsumx[d >> 8] + atomicAdd(&g_rowptr[d], 1);
            g_epair[pos] = make_int2(sv, __float_as_int(c));
        }
    }
}

// ---------------------------------------------------------------------------
// FAT kernel: blocks [0, bG) do gemm1; blocks [bG, bG+bE4) do reorder.
// Both are independent; co-residency overlaps FMA-bound and atomic-bound work.
// ---------------------------------------------------------------------------
__global__ void __launch_bounds__(256) k_gemm_reorder(const float* __restrict__ X,
                                                      const float* __restrict__ W,
                                                      float* __restrict__ H,
                                                      const int* __restrict__ src,
                                                      const int* __restrict__ dst,
                                                      const float* __restrict__ w,
                                                      int bG) {
    __shared__ float Xs[64][68];
    __shared__ float Ws[DD][DD];
    if ((int)blockIdx.x < bG) {
        gemm_body(X, W, H, blockIdx.x * 64, Xs, Ws);
    } else {
        reorder_body(src, dst, w, blockIdx.x - bG);
    }
}

// Plain 64-row GEMM (layer 2)
__global__ void __launch_bounds__(256) k_gemm(const float* __restrict__ X,
                                              const float* __restrict__ W,
                                              float* __restrict__ H) {
    __shared__ float Xs[64][68];
    __shared__ float Ws[DD][DD];
    gemm_body(X, W, H, blockIdx.x * 64, Xs, Ws);
}

// ---------------------------------------------------------------------------
// CSR gather, 1 warp/node, float2/lane, 8-edge prefetched batches.
// epair holds (src, coef-bits). (proven 58us path)
// ---------------------------------------------------------------------------
__global__ void k_gather(const float* __restrict__ H, float* __restrict__ OUT,
                         const float* __restrict__ b, int do_relu) {
    int n = (blockIdx.x * blockDim.x + threadIdx.x) >> 5;
    if (n >= NN) return;
    int lane = threadIdx.x & 31;
    const float2* __restrict__ H2 = reinterpret_cast<const float2*>(H);

    int beg = (n == 0) ? 0 : (g_rowptr[n - 1] + g_bsumx[(n - 1) >> 8]);
    int end = g_rowptr[n] + g_bsumx[n >> 8];

    float2 a0 = make_float2(0.f, 0.f), a1 = a0, a2 = a0, a3 = a0;

    int2 p[8];
#pragma unroll
    for (int j = 0; j < 8; j++)
        p[j] = (beg + j < end) ? g_epair[beg + j] : make_int2(0, 0);

    int e = beg;
    while (e + 8 <= end) {
        float2 f[8];
#pragma unroll
        for (int j = 0; j < 8; j++)
            f[j] = H2[((size_t)p[j].x << 5) + lane];

        int2 np[8];
#pragma unroll
        for (int j = 0; j < 8; j++)
            np[j] = (e + 8 + j < end) ? g_epair[e + 8 + j] : make_int2(0, 0);

#pragma unroll
        for (int j = 0; j < 8; j++) {
            float c = __int_as_float(p[j].y);
            float2* a = (j & 3) == 0 ? &a0 : (j & 3) == 1 ? &a1 : (j & 3) == 2 ? &a2 : &a3;
            a->x = fmaf(c, f[j].x, a->x);
            a->y = fmaf(c, f[j].y, a->y);
        }
#pragma unroll
        for (int j = 0; j < 8; j++) p[j] = np[j];
        e += 8;
    }

    int rem = end - e;
#pragma unroll
    for (int j = 0; j < 8; j++) {
        if (j < rem) {
            float2 f = H2[((size_t)p[j].x << 5) + lane];
            float c = __int_as_float(p[j].y);
            float2* a = (j & 3) == 0 ? &a0 : (j & 3) == 1 ? &a1 : (j & 3) == 2 ? &a2 : &a3;
            a->x = fmaf(c, f.x, a->x);
            a->y = fmaf(c, f.y, a->y);
        }
    }

    float dn = g_dis[n];
    float s2 = dn * dn;
    float2 hs = H2[((size_t)n << 5) + lane];
    float2 bv = reinterpret_cast<const float2*>(b)[lane];

    float ox = (a0.x + a1.x) + (a2.x + a3.x) + hs.x * s2 + bv.x;
    float oy = (a0.y + a1.y) + (a2.y + a3.y) + hs.y * s2 + bv.y;
    if (do_relu) { ox = fmaxf(ox, 0.f); oy = fmaxf(oy, 0.f); }
    reinterpret_cast<float2*>(OUT)[((size_t)n << 5) + lane] = make_float2(ox, oy);
}

// ---------------------------------------------------------------------------
// Launch (fat kernel at position #4 -> profiled by ncu)
// ---------------------------------------------------------------------------
extern "C" void kernel_launch(void* const* d_in, const int* in_sizes, int n_in,
                              void* d_out, int out_size) {
    const float* x  = (const float*)d_in[0];
    const int*   ei = (const int*)d_in[1];
    const float* w  = (const float*)d_in[2];
    const float* W1 = (const float*)d_in[3];
    const float* b1 = (const float*)d_in[4];
    const float* W2 = (const float*)d_in[5];
    const float* b2 = (const float*)d_in[6];
    float* out = (float*)d_out;

    const int* src = ei;
    const int* dst = ei + EE;

    float* h_p;   cudaGetSymbolAddress((void**)&h_p,   g_h);
    float* agg_p; cudaGetSymbolAddress((void**)&agg_p, g_agg);

    const int T = 256;
    int bE4 = (EE / 4 + T - 1) / T;            // 1221
    int bG  = (NN + 63) / 64;                  // 1563
    int bW  = (NN * 32 + T - 1) / T;           // 12500 (1 warp/node)

    k_hist<<<bE4, T>>>(dst, w);                            // #1
    k_scan1<<<NB, 256>>>();                                // #2
    k_scan2<<<1, 512>>>();                                 // #3
    k_gemm_reorder<<<bG + bE4, T>>>(x, W1, h_p,
                                    src, dst, w, bG);      // #4  <-- profiled
    k_gather<<<bW, T>>>(h_p, agg_p, b1, 1);                // #5
    k_gemm<<<bG, T>>>(agg_p, W2, h_p);                     // #6
    k_gather<<<bW, T>>>(h_p, out, b2, 0);                  // #7
}

// round 11
// speedup vs baseline: 1.0160x; 1.0160x over previous
#include <cuda_runtime.h>
#include <cuda_bf16.h>
#include <cstdint>

#define NN 100000
#define EE 1250000
#define DD 64
#define NB ((NN + 255) / 256)   // 391 scan blocks

// ---------------------------------------------------------------------------
// Scratch (__device__ globals; zero-initialized at load; self-restoring)
// ---------------------------------------------------------------------------
__device__ int   g_cnt[NN];                // edge count per dst (cleared by scan1)
__device__ float g_deg[NN];                // weighted degree (cleared by scan1)
__device__ float g_dis[NN];                // deg^{-1/2}
__device__ int   g_rowptr[NN];             // local-exclusive after scan1; local-inclusive after reorder
__device__ int   g_bsum[NB];               // block totals (scan1)
__device__ int   g_bsumx[NB];              // exclusive block offsets (scan2)
__device__ int2  g_epair[EE];              // (src, coef-bits), dst-grouped
__device__ float g_h[NN * DD];             // gemm output buffer
__device__ float g_agg[NN * DD];           // gather output buffer

// ---------------------------------------------------------------------------
// Histogram: int count + float weighted degree, 4 edges/thread.
// ---------------------------------------------------------------------------
__global__ void k_hist(const int* __restrict__ dst, const float* __restrict__ w) {
    int t = blockIdx.x * blockDim.x + threadIdx.x;
    int e = t * 4;
    if (e + 4 <= EE) {
        int4 d = *reinterpret_cast<const int4*>(dst + e);
        float4 wv = *reinterpret_cast<const float4*>(w + e);
        atomicAdd(&g_cnt[d.x], 1);
        atomicAdd(&g_cnt[d.y], 1);
        atomicAdd(&g_cnt[d.z], 1);
        atomicAdd(&g_cnt[d.w], 1);
        atomicAdd(&g_deg[d.x], wv.x);
        atomicAdd(&g_deg[d.y], wv.y);
        atomicAdd(&g_deg[d.z], wv.z);
        atomicAdd(&g_deg[d.w], wv.w);
    } else {
        for (; e < EE; e++) {
            atomicAdd(&g_cnt[dst[e]], 1);
            atomicAdd(&g_deg[dst[e]], w[e]);
        }
    }
}

// ---------------------------------------------------------------------------
// scan1: read+clear cnt/deg, compute dis, block-local exclusive scan.
// ---------------------------------------------------------------------------
__global__ void k_scan1() {
    __shared__ int sh[256];
    int t = threadIdx.x;
    int i = blockIdx.x * 256 + t;
    int cnt = 0;
    if (i < NN) {
        cnt = g_cnt[i];
        g_cnt[i] = 0;                                  // restore for next run
        float deg = g_deg[i];
        g_deg[i] = 0.0f;                               // restore for next run
        g_dis[i] = rsqrtf(deg + 1.0f);
    }
    sh[t] = cnt;
    __syncthreads();
    for (int off = 1; off < 256; off <<= 1) {
        int u = (t >= off) ? sh[t - off] : 0;
        __syncthreads();
        sh[t] += u;
        __syncthreads();
    }
    if (i < NN) g_rowptr[i] = sh[t] - cnt;             // local exclusive
    if (t == 255) g_bsum[blockIdx.x] = sh[255];
}

// scan2: exclusive scan of 391 block totals -> g_bsumx
__global__ void k_scan2() {
    __shared__ int sh[512];
    int t = threadIdx.x;
    int v = (t < NB) ? g_bsum[t] : 0;
    sh[t] = v;
    __syncthreads();
    for (int off = 1; off < 512; off <<= 1) {
        int u = (t >= off) ? sh[t - off] : 0;
        __syncthreads();
        sh[t] += u;
        __syncthreads();
    }
    if (t < NB) g_bsumx[t] = sh[t] - v;
}

// ---------------------------------------------------------------------------
// Reorder: place (src, coef-bits), coef = dis[s]*w*dis[d]. 4 edges/thread.
// ---------------------------------------------------------------------------
__global__ void k_reorder(const int* __restrict__ src, const int* __restrict__ dst,
                          const float* __restrict__ w) {
    int t = blockIdx.x * blockDim.x + threadIdx.x;
    int e = t * 4;
    if (e + 4 <= EE) {
        int4 s = *reinterpret_cast<const int4*>(src + e);
        int4 d = *reinterpret_cast<const int4*>(dst + e);
        float4 wv = *reinterpret_cast<const float4*>(w + e);
        float c0 = g_dis[s.x] * wv.x * g_dis[d.x];
        float c1 = g_dis[s.y] * wv.y * g_dis[d.y];
        float c2 = g_dis[s.z] * wv.z * g_dis[d.z];
        float c3 = g_dis[s.w] * wv.w * g_dis[d.w];
        int p0 = g_bsumx[d.x >> 8] + atomicAdd(&g_rowptr[d.x], 1);
        int p1 = g_bsumx[d.y >> 8] + atomicAdd(&g_rowptr[d.y], 1);
        int p2 = g_bsumx[d.z >> 8] + atomicAdd(&g_rowptr[d.z], 1);
        int p3 = g_bsumx[d.w >> 8] + atomicAdd(&g_rowptr[d.w], 1);
        g_epair[p0] = make_int2(s.x, __float_as_int(c0));
        g_epair[p1] = make_int2(s.y, __float_as_int(c1));
        g_epair[p2] = make_int2(s.z, __float_as_int(c2));
        g_epair[p3] = make_int2(s.w, __float_as_int(c3));
    } else {
        for (; e < EE; e++) {
            int sv = src[e];
            int d = dst[e];
            float c = g_dis[sv] * w[e] * g_dis[d];
            int pos = g_bsumx[d >> 8] + atomicAdd(&g_rowptr[d], 1);
            g_epair[pos] = make_int2(sv, __float_as_int(c));
        }
    }
}

// ---------------------------------------------------------------------------
// 64-row GEMM: H[n][o] = sum_k X[n][k] * W[o][k]
// 256 threads: lane = row in 32-group, grp = 8-col group, 2x8 outputs/thread.
// ---------------------------------------------------------------------------
__global__ void __launch_bounds__(256) k_gemm(const float* __restrict__ X,
                                              const float* __restrict__ W,
                                              float* __restrict__ H) {
    __shared__ float Xs[64][68];
    __shared__ float Ws[DD][DD];      // Ws[k][o] = W[o][k]

    int tid = threadIdx.x;
    int lane = tid & 31;
    int grp  = tid >> 5;
    int row0 = blockIdx.x * 64;

    for (int idx = tid; idx < (DD * DD) / 4; idx += 256) {
        int o = idx >> 4;
        int k4 = (idx & 15) * 4;
        float4 v = *reinterpret_cast<const float4*>(W + o * DD + k4);
        Ws[k4 + 0][o] = v.x;
        Ws[k4 + 1][o] = v.y;
        Ws[k4 + 2][o] = v.z;
        Ws[k4 + 3][o] = v.w;
    }
    for (int idx = tid; idx < (64 * DD) / 4; idx += 256) {
        int r = idx >> 4;
        int k4 = (idx & 15) * 4;
        int row = row0 + r;
        float4 v = (row < NN) ? *reinterpret_cast<const float4*>(X + (size_t)row * DD + k4)
                              : make_float4(0.f, 0.f, 0.f, 0.f);
        *reinterpret_cast<float4*>(&Xs[r][k4]) = v;
    }
    __syncthreads();

    int c0 = grp * 8;
    float acc[2][8];
#pragma unroll
    for (int i = 0; i < 2; i++)
#pragma unroll
        for (int j = 0; j < 8; j++) acc[i][j] = 0.0f;

#pragma unroll 4
    for (int k = 0; k < DD; k++) {
        float xv0 = Xs[lane     ][k];
        float xv1 = Xs[lane + 32][k];
        float4 w0 = *reinterpret_cast<const float4*>(&Ws[k][c0]);
        float4 w1 = *reinterpret_cast<const float4*>(&Ws[k][c0 + 4]);
        float wv[8] = {w0.x, w0.y, w0.z, w0.w, w1.x, w1.y, w1.z, w1.w};
#pragma unroll
        for (int j = 0; j < 8; j++) {
            acc[0][j] = fmaf(xv0, wv[j], acc[0][j]);
            acc[1][j] = fmaf(xv1, wv[j], acc[1][j]);
        }
    }

#pragma unroll
    for (int i = 0; i < 2; i++) {
        int row = row0 + lane + i * 32;
        if (row < NN) {
            float* hp = H + (size_t)row * DD + c0;
            *reinterpret_cast<float4*>(hp)     = make_float4(acc[i][0], acc[i][1], acc[i][2], acc[i][3]);
            *reinterpret_cast<float4*>(hp + 4) = make_float4(acc[i][4], acc[i][5], acc[i][6], acc[i][7]);
        }
    }
}

// ---------------------------------------------------------------------------
// CSR gather, 1 warp/node, float2/lane. Lane-parallel epair load + shfl
// distribution (low regs -> high occupancy); feature loads in MLP-8 groups.
// ---------------------------------------------------------------------------
__global__ void __launch_bounds__(256) k_gather(const float* __restrict__ H,
                                                float* __restrict__ OUT,
                                                const float* __restrict__ b,
                                                int do_relu) {
    int n = (blockIdx.x * blockDim.x + threadIdx.x) >> 5;
    if (n >= NN) return;
    int lane = threadIdx.x & 31;
    const float2* __restrict__ H2 = reinterpret_cast<const float2*>(H);

    int beg = (n == 0) ? 0 : (g_rowptr[n - 1] + g_bsumx[(n - 1) >> 8]);
    int end = g_rowptr[n] + g_bsumx[n >> 8];
    int cnt = end - beg;

    float2 a0 = make_float2(0.f, 0.f), a1 = a0;

    for (int base = 0; base < cnt; base += 32) {
        int m = cnt - base;
        if (m > 32) m = 32;
        int2 p = make_int2(0, 0);
        if (lane < m) p = g_epair[beg + base + lane];   // one coalesced row load

        for (int j0 = 0; j0 < m; j0 += 8) {
            float2 f[8];
            float cc[8];
#pragma unroll
            for (int j = 0; j < 8; j++) {
                int idx = j0 + j;
                int sv  = __shfl_sync(0xffffffffu, p.x, idx & 31);
                int cb  = __shfl_sync(0xffffffffu, p.y, idx & 31);
                bool vld = idx < m;
                cc[j] = vld ? __int_as_float(cb) : 0.0f;
                f[j] = vld ? H2[((size_t)sv << 5) + lane] : make_float2(0.f, 0.f);
            }
#pragma unroll
            for (int j = 0; j < 8; j++) {
                float2* a = (j & 1) ? &a1 : &a0;
                a->x = fmaf(cc[j], f[j].x, a->x);
                a->y = fmaf(cc[j], f[j].y, a->y);
            }
        }
    }

    float dn = g_dis[n];
    float s2 = dn * dn;
    float2 hs = H2[((size_t)n << 5) + lane];
    float2 bv = reinterpret_cast<const float2*>(b)[lane];

    float ox = a0.x + a1.x + hs.x * s2 + bv.x;
    float oy = a0.y + a1.y + hs.y * s2 + bv.y;
    if (do_relu) { ox = fmaxf(ox, 0.f); oy = fmaxf(oy, 0.f); }
    reinterpret_cast<float2*>(OUT)[((size_t)n << 5) + lane] = make_float2(ox, oy);
}

// ---------------------------------------------------------------------------
// Launch (64-row k_gemm at position #4 -> profiled by ncu)
// ---------------------------------------------------------------------------
extern "C" void kernel_launch(void* const* d_in, const int* in_sizes, int n_in,
                              void* d_out, int out_size) {
    const float* x  = (const float*)d_in[0];
    const int*   ei = (const int*)d_in[1];
    const float* w  = (const float*)d_in[2];
    const float* W1 = (const float*)d_in[3];
    const float* b1 = (const float*)d_in[4];
    const float* W2 = (const float*)d_in[5];
    const float* b2 = (const float*)d_in[6];
    float* out = (float*)d_out;

    const int* src = ei;
    const int* dst = ei + EE;

    float* h_p;   cudaGetSymbolAddress((void**)&h_p,   g_h);
    float* agg_p; cudaGetSymbolAddress((void**)&agg_p, g_agg);

    const int T = 256;
    int bE4 = (EE / 4 + T - 1) / T;            // 1221
    int bG  = (NN + 63) / 64;                  // 1563
    int bW  = (NN * 32 + T - 1) / T;           // 12500 (1 warp/node)

    k_hist<<<bE4, T>>>(dst, w);                // #1
    k_scan1<<<NB, 256>>>();                    // #2
    k_scan2<<<1, 512>>>();                     // #3
    k_gemm<<<bG, T>>>(x, W1, h_p);             // #4  <-- profiled (independent of build)
    k_reorder<<<bE4, T>>>(src, dst, w);        // #5
    k_gather<<<bW, T>>>(h_p, agg_p, b1, 1);    // #6
    k_gemm<<<bG, T>>>(agg_p, W2, h_p);         // #7
    k_gather<<<bW, T>>>(h_p, out, b2, 0);      // #8
}

// round 12
// speedup vs baseline: 1.1906x; 1.1719x over previous
#include <cuda_runtime.h>
#include <cuda_bf16.h>
#include <cstdint>

#define NN 100000
#define EE 1250000
#define DD 64
#define NB ((NN + 255) / 256)   // 391 scan blocks
#define EPAD (EE + 8 * NN)      // padded edge capacity

// ---------------------------------------------------------------------------
// Scratch (__device__ globals; zero-initialized at load; self-restoring)
// ---------------------------------------------------------------------------
__device__ int   g_cnt[NN];                // hist count (cleared by scan1)
__device__ float g_deg[NN];                // weighted degree (cleared by scan1)
__device__ float g_dis[NN];                // deg^{-1/2}
__device__ int   g_fill[NN];               // reorder cursor (cleared by scan1)
__device__ int   g_rowstart[NN];           // padded local-exclusive start
__device__ int   g_rowend[NN];             // padded local end (start + cnt_padded)
__device__ int   g_bsum[NB];               // padded block totals
__device__ int   g_bsumx[NB];              // exclusive block offsets
__device__ __align__(16) int2 g_epair[EPAD]; // (src*256, coef-bits); pad slots stay (0,0)
__device__ float g_h[NN * DD];             // gemm output buffer
__device__ float g_agg[NN * DD];           // gather output buffer

// ---------------------------------------------------------------------------
// Histogram: int count + float weighted degree, 4 edges/thread.
// ---------------------------------------------------------------------------
__global__ void k_hist(const int* __restrict__ dst, const float* __restrict__ w) {
    int t = blockIdx.x * blockDim.x + threadIdx.x;
    int e = t * 4;
    if (e + 4 <= EE) {
        int4 d = *reinterpret_cast<const int4*>(dst + e);
        float4 wv = *reinterpret_cast<const float4*>(w + e);
        atomicAdd(&g_cnt[d.x], 1);
        atomicAdd(&g_cnt[d.y], 1);
        atomicAdd(&g_cnt[d.z], 1);
        atomicAdd(&g_cnt[d.w], 1);
        atomicAdd(&g_deg[d.x], wv.x);
        atomicAdd(&g_deg[d.y], wv.y);
        atomicAdd(&g_deg[d.z], wv.z);
        atomicAdd(&g_deg[d.w], wv.w);
    } else {
        for (; e < EE; e++) {
            atomicAdd(&g_cnt[dst[e]], 1);
            atomicAdd(&g_deg[dst[e]], w[e]);
        }
    }
}

// ---------------------------------------------------------------------------
// scan1: read+clear cnt/deg/fill, compute dis, scan PADDED counts.
// ---------------------------------------------------------------------------
__global__ void k_scan1() {
    __shared__ int sh[256];
    int t = threadIdx.x;
    int i = blockIdx.x * 256 + t;
    int cntp = 0;
    if (i < NN) {
        int cnt = g_cnt[i];
        g_cnt[i] = 0;                                  // restore
        g_fill[i] = 0;                                 // reorder cursor reset
        float deg = g_deg[i];
        g_deg[i] = 0.0f;                               // restore
        g_dis[i] = rsqrtf(deg + 1.0f);
        cntp = (cnt + 7) & ~7;                         // pad to multiple of 8
    }
    sh[t] = cntp;
    __syncthreads();
    for (int off = 1; off < 256; off <<= 1) {
        int u = (t >= off) ? sh[t - off] : 0;
        __syncthreads();
        sh[t] += u;
        __syncthreads();
    }
    if (i < NN) {
        g_rowstart[i] = sh[t] - cntp;                  // local exclusive (mult of 8)
        g_rowend[i]   = sh[t];                         // local inclusive padded
    }
    if (t == 255) g_bsum[blockIdx.x] = sh[255];
}

// scan2: exclusive scan of 391 padded block totals -> g_bsumx
__global__ void k_scan2() {
    __shared__ int sh[512];
    int t = threadIdx.x;
    int v = (t < NB) ? g_bsum[t] : 0;
    sh[t] = v;
    __syncthreads();
    for (int off = 1; off < 512; off <<= 1) {
        int u = (t >= off) ? sh[t - off] : 0;
        __syncthreads();
        sh[t] += u;
        __syncthreads();
    }
    if (t < NB) g_bsumx[t] = sh[t] - v;
}

// ---------------------------------------------------------------------------
// Reorder: place (src*256, coef-bits) into padded CSR slots. 4 edges/thread.
// ---------------------------------------------------------------------------
__global__ void k_reorder(const int* __restrict__ src, const int* __restrict__ dst,
                          const float* __restrict__ w) {
    int t = blockIdx.x * blockDim.x + threadIdx.x;
    int e = t * 4;
    if (e + 4 <= EE) {
        int4 s = *reinterpret_cast<const int4*>(src + e);
        int4 d = *reinterpret_cast<const int4*>(dst + e);
        float4 wv = *reinterpret_cast<const float4*>(w + e);
        float c0 = g_dis[s.x] * wv.x * g_dis[d.x];
        float c1 = g_dis[s.y] * wv.y * g_dis[d.y];
        float c2 = g_dis[s.z] * wv.z * g_dis[d.z];
        float c3 = g_dis[s.w] * wv.w * g_dis[d.w];
        int p0 = g_rowstart[d.x] + g_bsumx[d.x >> 8] + atomicAdd(&g_fill[d.x], 1);
        int p1 = g_rowstart[d.y] + g_bsumx[d.y >> 8] + atomicAdd(&g_fill[d.y], 1);
        int p2 = g_rowstart[d.z] + g_bsumx[d.z >> 8] + atomicAdd(&g_fill[d.z], 1);
        int p3 = g_rowstart[d.w] + g_bsumx[d.w >> 8] + atomicAdd(&g_fill[d.w], 1);
        g_epair[p0] = make_int2(s.x << 8, __float_as_int(c0));
        g_epair[p1] = make_int2(s.y << 8, __float_as_int(c1));
        g_epair[p2] = make_int2(s.z << 8, __float_as_int(c2));
        g_epair[p3] = make_int2(s.w << 8, __float_as_int(c3));
    } else {
        for (; e < EE; e++) {
            int sv = src[e];
            int d = dst[e];
            float c = g_dis[sv] * w[e] * g_dis[d];
            int pos = g_rowstart[d] + g_bsumx[d >> 8] + atomicAdd(&g_fill[d], 1);
            g_epair[pos] = make_int2(sv << 8, __float_as_int(c));
        }
    }
}

// ---------------------------------------------------------------------------
// Register-blocked GEMM (R7-proven, 41us): H[n][o] = sum_k X[n][k]*W[o][k]
// 256 threads, 128x64 tile, 4x8 outputs/thread.
// ---------------------------------------------------------------------------
__global__ void __launch_bounds__(256) k_gemm(const float* __restrict__ X,
                                              const float* __restrict__ W,
                                              float* __restrict__ H) {
    __shared__ float Xs[128][65];
    __shared__ float Ws[DD][DD];      // Ws[k][o] = W[o][k]

    int tid = threadIdx.x;
    int lane = tid & 31;
    int grp  = tid >> 5;
    int row0 = blockIdx.x * 128;

    for (int idx = tid; idx < (DD * DD) / 4; idx += 256) {
        int o = idx >> 4;
        int k4 = (idx & 15) * 4;
        float4 v = *reinterpret_cast<const float4*>(W + o * DD + k4);
        Ws[k4 + 0][o] = v.x;
        Ws[k4 + 1][o] = v.y;
        Ws[k4 + 2][o] = v.z;
        Ws[k4 + 3][o] = v.w;
    }
    for (int idx = tid; idx < (128 * DD) / 4; idx += 256) {
        int r = idx >> 4;
        int k4 = (idx & 15) * 4;
        int row = row0 + r;
        float4 v = (row < NN) ? *reinterpret_cast<const float4*>(X + (size_t)row * DD + k4)
                              : make_float4(0.f, 0.f, 0.f, 0.f);
        Xs[r][k4 + 0] = v.x;
        Xs[r][k4 + 1] = v.y;
        Xs[r][k4 + 2] = v.z;
        Xs[r][k4 + 3] = v.w;
    }
    __syncthreads();

    int c0 = grp * 8;
    float acc[4][8];
#pragma unroll
    for (int i = 0; i < 4; i++)
#pragma unroll
        for (int j = 0; j < 8; j++) acc[i][j] = 0.0f;

#pragma unroll 4
    for (int k = 0; k < DD; k++) {
        float xv0 = Xs[lane      ][k];
        float xv1 = Xs[lane + 32 ][k];
        float xv2 = Xs[lane + 64 ][k];
        float xv3 = Xs[lane + 96 ][k];
        float4 w0 = *reinterpret_cast<const float4*>(&Ws[k][c0]);
        float4 w1 = *reinterpret_cast<const float4*>(&Ws[k][c0 + 4]);
        float wv[8] = {w0.x, w0.y, w0.z, w0.w, w1.x, w1.y, w1.z, w1.w};
#pragma unroll
        for (int j = 0; j < 8; j++) {
            acc[0][j] = fmaf(xv0, wv[j], acc[0][j]);
            acc[1][j] = fmaf(xv1, wv[j], acc[1][j]);
            acc[2][j] = fmaf(xv2, wv[j], acc[2][j]);
            acc[3][j] = fmaf(xv3, wv[j], acc[3][j]);
        }
    }

#pragma unroll
    for (int i = 0; i < 4; i++) {
        int row = row0 + lane + i * 32;
        if (row < NN) {
            float* hp = H + (size_t)row * DD + c0;
            *reinterpret_cast<float4*>(hp)     = make_float4(acc[i][0], acc[i][1], acc[i][2], acc[i][3]);
            *reinterpret_cast<float4*>(hp + 4) = make_float4(acc[i][4], acc[i][5], acc[i][6], acc[i][7]);
        }
    }
}

// ---------------------------------------------------------------------------
// CSR gather, 1 warp/node, float2/lane. Rows padded to 8 -> NO predication,
// no tail. Epairs via int4 broadcast loads; feature addr = base + byteoff.
// ---------------------------------------------------------------------------
__global__ void __launch_bounds__(256) k_gather(const float* __restrict__ H,
                                                float* __restrict__ OUT,
                                                const float* __restrict__ b,
                                                int do_relu) {
    int n = (blockIdx.x * blockDim.x + threadIdx.x) >> 5;
    if (n >= NN) return;
    int lane = threadIdx.x & 31;
    const char* __restrict__ Hb = reinterpret_cast<const char*>(H);
    unsigned loff = (unsigned)lane * 8u;

    int bo = g_bsumx[n >> 8];
    int beg = g_rowstart[n] + bo;
    int end = g_rowend[n] + bo;

    float2 a0 = make_float2(0.f, 0.f), a1 = a0, a2 = a0, a3 = a0;

    for (int e = beg; e < end; e += 8) {
        int4 q0 = *reinterpret_cast<const int4*>(&g_epair[e]);      // edges 0,1
        int4 q1 = *reinterpret_cast<const int4*>(&g_epair[e + 2]);  // edges 2,3
        int4 q2 = *reinterpret_cast<const int4*>(&g_epair[e + 4]);  // edges 4,5
        int4 q3 = *reinterpret_cast<const int4*>(&g_epair[e + 6]);  // edges 6,7

        float2 f0 = *reinterpret_cast<const float2*>(Hb + (unsigned)q0.x + loff);
        float2 f1 = *reinterpret_cast<const float2*>(Hb + (unsigned)q0.z + loff);
        float2 f2 = *reinterpret_cast<const float2*>(Hb + (unsigned)q1.x + loff);
        float2 f3 = *reinterpret_cast<const float2*>(Hb + (unsigned)q1.z + loff);
        float2 f4 = *reinterpret_cast<const float2*>(Hb + (unsigned)q2.x + loff);
        float2 f5 = *reinterpret_cast<const float2*>(Hb + (unsigned)q2.z + loff);
        float2 f6 = *reinterpret_cast<const float2*>(Hb + (unsigned)q3.x + loff);
        float2 f7 = *reinterpret_cast<const float2*>(Hb + (unsigned)q3.z + loff);

        float c0 = __int_as_float(q0.y), c1 = __int_as_float(q0.w);
        float c2 = __int_as_float(q1.y), c3 = __int_as_float(q1.w);
        float c4 = __int_as_float(q2.y), c5 = __int_as_float(q2.w);
        float c6 = __int_as_float(q3.y), c7 = __int_as_float(q3.w);

        a0.x = fmaf(c0, f0.x, a0.x); a0.y = fmaf(c0, f0.y, a0.y);
        a1.x = fmaf(c1, f1.x, a1.x); a1.y = fmaf(c1, f1.y, a1.y);
        a2.x = fmaf(c2, f2.x, a2.x); a2.y = fmaf(c2, f2.y, a2.y);
        a3.x = fmaf(c3, f3.x, a3.x); a3.y = fmaf(c3, f3.y, a3.y);
        a0.x = fmaf(c4, f4.x, a0.x); a0.y = fmaf(c4, f4.y, a0.y);
        a1.x = fmaf(c5, f5.x, a1.x); a1.y = fmaf(c5, f5.y, a1.y);
        a2.x = fmaf(c6, f6.x, a2.x); a2.y = fmaf(c6, f6.y, a2.y);
        a3.x = fmaf(c7, f7.x, a3.x); a3.y = fmaf(c7, f7.y, a3.y);
    }

    float dn = g_dis[n];
    float s2 = dn * dn;
    float2 hs = *reinterpret_cast<const float2*>(Hb + ((unsigned)n << 8) + loff);
    float2 bv = reinterpret_cast<const float2*>(b)[lane];

    float ox = (a0.x + a1.x) + (a2.x + a3.x) + hs.x * s2 + bv.x;
    float oy = (a0.y + a1.y) + (a2.y + a3.y) + hs.y * s2 + bv.y;
    if (do_relu) { ox = fmaxf(ox, 0.f); oy = fmaxf(oy, 0.f); }
    reinterpret_cast<float2*>(OUT)[((size_t)n << 5) + lane] = make_float2(ox, oy);
}

// ---------------------------------------------------------------------------
// Launch (k_reorder at position #4 -> profiled by ncu)
// ---------------------------------------------------------------------------
extern "C" void kernel_launch(void* const* d_in, const int* in_sizes, int n_in,
                              void* d_out, int out_size) {
    const float* x  = (const float*)d_in[0];
    const int*   ei = (const int*)d_in[1];
    const float* w  = (const float*)d_in[2];
    const float* W1 = (const float*)d_in[3];
    const float* b1 = (const float*)d_in[4];
    const float* W2 = (const float*)d_in[5];
    const float* b2 = (const float*)d_in[6];
    float* out = (float*)d_out;

    const int* src = ei;
    const int* dst = ei + EE;

    float* h_p;   cudaGetSymbolAddress((void**)&h_p,   g_h);
    float* agg_p; cudaGetSymbolAddress((void**)&agg_p, g_agg);

    const int T = 256;
    int bE4 = (EE / 4 + T - 1) / T;            // 1221
    int bG  = (NN + 127) / 128;                // 782
    int bW  = (NN * 32 + T - 1) / T;           // 12500 (1 warp/node)

    k_hist<<<bE4, T>>>(dst, w);                // #1
    k_scan1<<<NB, 256>>>();                    // #2
    k_scan2<<<1, 512>>>();                     // #3
    k_reorder<<<bE4, T>>>(src, dst, w);        // #4  <-- profiled
    k_gemm<<<bG, T>>>(x, W1, h_p);             // #5
    k_gather<<<bW, T>>>(h_p, agg_p, b1, 1);    // #6
    k_gemm<<<bG, T>>>(agg_p, W2, h_p);         // #7
    k_gather<<<bW, T>>>(h_p, out, b2, 0);      // #8
}

// round 13
// speedup vs baseline: 1.2322x; 1.0350x over previous
#include <cuda_runtime.h>
#include <cuda_bf16.h>
#include <cstdint>

#define NN 100000
#define EE 1250000
#define DD 64
#define NB ((NN + 255) / 256)   // 391 scan blocks
#define EPAD (EE + 8 * NN)      // padded edge capacity

// ---------------------------------------------------------------------------
// Scratch (__device__ globals; zero-initialized at load; self-restoring)
// ---------------------------------------------------------------------------
__device__ int   g_cnt[NN];                // hist count (cleared by scan1)
__device__ float g_deg[NN];                // weighted degree (cleared by scan1)
__device__ float g_dis[NN];                // deg^{-1/2}
__device__ int   g_fill[NN];               // reorder cursor (cleared by scan1)
__device__ int   g_rowstart[NN];           // padded start (global after scan3)
__device__ int   g_rowend[NN];             // padded end (global after scan3)
__device__ int   g_bsum[NB];               // padded block totals
__device__ int   g_bsumx[NB];              // exclusive block offsets
__device__ __align__(16) int2 g_epair[EPAD]; // (src*256, coef-bits); pad slots stay (0,0)
__device__ float g_h[NN * DD];             // gemm output buffer
__device__ float g_agg[NN * DD];           // gather output buffer

// ---------------------------------------------------------------------------
// Histogram: int count + float weighted degree, 4 edges/thread.
// ---------------------------------------------------------------------------
__global__ void k_hist(const int* __restrict__ dst, const float* __restrict__ w) {
    int t = blockIdx.x * blockDim.x + threadIdx.x;
    int e = t * 4;
    if (e + 4 <= EE) {
        int4 d = *reinterpret_cast<const int4*>(dst + e);
        float4 wv = *reinterpret_cast<const float4*>(w + e);
        atomicAdd(&g_cnt[d.x], 1);
        atomicAdd(&g_cnt[d.y], 1);
        atomicAdd(&g_cnt[d.z], 1);
        atomicAdd(&g_cnt[d.w], 1);
        atomicAdd(&g_deg[d.x], wv.x);
        atomicAdd(&g_deg[d.y], wv.y);
        atomicAdd(&g_deg[d.z], wv.z);
        atomicAdd(&g_deg[d.w], wv.w);
    } else {
        for (; e < EE; e++) {
            atomicAdd(&g_cnt[dst[e]], 1);
            atomicAdd(&g_deg[dst[e]], w[e]);
        }
    }
}

// ---------------------------------------------------------------------------
// scan1: read+clear cnt/deg/fill, compute dis, scan PADDED counts.
// ---------------------------------------------------------------------------
__global__ void k_scan1() {
    __shared__ int sh[256];
    int t = threadIdx.x;
    int i = blockIdx.x * 256 + t;
    int cntp = 0;
    if (i < NN) {
        int cnt = g_cnt[i];
        g_cnt[i] = 0;                                  // restore
        g_fill[i] = 0;                                 // reorder cursor reset
        float deg = g_deg[i];
        g_deg[i] = 0.0f;                               // restore
        g_dis[i] = rsqrtf(deg + 1.0f);
        cntp = (cnt + 7) & ~7;                         // pad to multiple of 8
    }
    sh[t] = cntp;
    __syncthreads();
    for (int off = 1; off < 256; off <<= 1) {
        int u = (t >= off) ? sh[t - off] : 0;
        __syncthreads();
        sh[t] += u;
        __syncthreads();
    }
    if (i < NN) {
        g_rowstart[i] = sh[t] - cntp;                  // local exclusive (mult of 8)
        g_rowend[i]   = sh[t];                         // local inclusive padded
    }
    if (t == 255) g_bsum[blockIdx.x] = sh[255];
}

// scan2: exclusive scan of 391 padded block totals -> g_bsumx
__global__ void k_scan2() {
    __shared__ int sh[512];
    int t = threadIdx.x;
    int v = (t < NB) ? g_bsum[t] : 0;
    sh[t] = v;
    __syncthreads();
    for (int off = 1; off < 512; off <<= 1) {
        int u = (t >= off) ? sh[t - off] : 0;
        __syncthreads();
        sh[t] += u;
        __syncthreads();
    }
    if (t < NB) g_bsumx[t] = sh[t] - v;
}

// scan3: fold block offsets into rowstart/rowend (globalize)
__global__ void k_scan3() {
    int i = blockIdx.x * 256 + threadIdx.x;
    if (i < NN) {
        int off = g_bsumx[i >> 8];
        g_rowstart[i] += off;
        g_rowend[i]   += off;
    }
}

// ---------------------------------------------------------------------------
// Reorder: place (src*256, coef-bits) into padded CSR slots. 4 edges/thread.
// One rowstart load + one atomic per edge.
// ---------------------------------------------------------------------------
__global__ void k_reorder(const int* __restrict__ src, const int* __restrict__ dst,
                          const float* __restrict__ w) {
    int t = blockIdx.x * blockDim.x + threadIdx.x;
    int e = t * 4;
    if (e + 4 <= EE) {
        int4 s = *reinterpret_cast<const int4*>(src + e);
        int4 d = *reinterpret_cast<const int4*>(dst + e);
        float4 wv = *reinterpret_cast<const float4*>(w + e);
        float c0 = g_dis[s.x] * wv.x * g_dis[d.x];
        float c1 = g_dis[s.y] * wv.y * g_dis[d.y];
        float c2 = g_dis[s.z] * wv.z * g_dis[d.z];
        float c3 = g_dis[s.w] * wv.w * g_dis[d.w];
        int p0 = g_rowstart[d.x] + atomicAdd(&g_fill[d.x], 1);
        int p1 = g_rowstart[d.y] + atomicAdd(&g_fill[d.y], 1);
        int p2 = g_rowstart[d.z] + atomicAdd(&g_fill[d.z], 1);
        int p3 = g_rowstart[d.w] + atomicAdd(&g_fill[d.w], 1);
        g_epair[p0] = make_int2(s.x << 8, __float_as_int(c0));
        g_epair[p1] = make_int2(s.y << 8, __float_as_int(c1));
        g_epair[p2] = make_int2(s.z << 8, __float_as_int(c2));
        g_epair[p3] = make_int2(s.w << 8, __float_as_int(c3));
    } else {
        for (; e < EE; e++) {
            int sv = src[e];
            int d = dst[e];
            float c = g_dis[sv] * w[e] * g_dis[d];
            int pos = g_rowstart[d] + atomicAdd(&g_fill[d], 1);
            g_epair[pos] = make_int2(sv << 8, __float_as_int(c));
        }
    }
}

// ---------------------------------------------------------------------------
// Register-blocked GEMM (R7-proven, 41us): H[n][o] = sum_k X[n][k]*W[o][k]
// ---------------------------------------------------------------------------
__global__ void __launch_bounds__(256) k_gemm(const float* __restrict__ X,
                                              const float* __restrict__ W,
                                              float* __restrict__ H) {
    __shared__ float Xs[128][65];
    __shared__ float Ws[DD][DD];      // Ws[k][o] = W[o][k]

    int tid = threadIdx.x;
    int lane = tid & 31;
    int grp  = tid >> 5;
    int row0 = blockIdx.x * 128;

    for (int idx = tid; idx < (DD * DD) / 4; idx += 256) {
        int o = idx >> 4;
        int k4 = (idx & 15) * 4;
        float4 v = *reinterpret_cast<const float4*>(W + o * DD + k4);
        Ws[k4 + 0][o] = v.x;
        Ws[k4 + 1][o] = v.y;
        Ws[k4 + 2][o] = v.z;
        Ws[k4 + 3][o] = v.w;
    }
    for (int idx = tid; idx < (128 * DD) / 4; idx += 256) {
        int r = idx >> 4;
        int k4 = (idx & 15) * 4;
        int row = row0 + r;
        float4 v = (row < NN) ? *reinterpret_cast<const float4*>(X + (size_t)row * DD + k4)
                              : make_float4(0.f, 0.f, 0.f, 0.f);
        Xs[r][k4 + 0] = v.x;
        Xs[r][k4 + 1] = v.y;
        Xs[r][k4 + 2] = v.z;
        Xs[r][k4 + 3] = v.w;
    }
    __syncthreads();

    int c0 = grp * 8;
    float acc[4][8];
#pragma unroll
    for (int i = 0; i < 4; i++)
#pragma unroll
        for (int j = 0; j < 8; j++) acc[i][j] = 0.0f;

#pragma unroll 4
    for (int k = 0; k < DD; k++) {
        float xv0 = Xs[lane      ][k];
        float xv1 = Xs[lane + 32 ][k];
        float xv2 = Xs[lane + 64 ][k];
        float xv3 = Xs[lane + 96 ][k];
        float4 w0 = *reinterpret_cast<const float4*>(&Ws[k][c0]);
        float4 w1 = *reinterpret_cast<const float4*>(&Ws[k][c0 + 4]);
        float wv[8] = {w0.x, w0.y, w0.z, w0.w, w1.x, w1.y, w1.z, w1.w};
#pragma unroll
        for (int j = 0; j < 8; j++) {
            acc[0][j] = fmaf(xv0, wv[j], acc[0][j]);
            acc[1][j] = fmaf(xv1, wv[j], acc[1][j]);
            acc[2][j] = fmaf(xv2, wv[j], acc[2][j]);
            acc[3][j] = fmaf(xv3, wv[j], acc[3][j]);
        }
    }

#pragma unroll
    for (int i = 0; i < 4; i++) {
        int row = row0 + lane + i * 32;
        if (row < NN) {
            float* hp = H + (size_t)row * DD + c0;
            *reinterpret_cast<float4*>(hp)     = make_float4(acc[i][0], acc[i][1], acc[i][2], acc[i][3]);
            *reinterpret_cast<float4*>(hp + 4) = make_float4(acc[i][4], acc[i][5], acc[i][6], acc[i][7]);
        }
    }
}

// ---------------------------------------------------------------------------
// CSR gather, 1 warp/node, float2/lane. Padded rows: no predication, no tail.
// ---------------------------------------------------------------------------
__global__ void __launch_bounds__(256) k_gather(const float* __restrict__ H,
                                                float* __restrict__ OUT,
                                                const float* __restrict__ b,
                                                int do_relu) {
    int n = (blockIdx.x * blockDim.x + threadIdx.x) >> 5;
    if (n >= NN) return;
    int lane = threadIdx.x & 31;
    const char* __restrict__ Hb = reinterpret_cast<const char*>(H);
    unsigned loff = (unsigned)lane * 8u;

    int beg = g_rowstart[n];
    int end = g_rowend[n];

    float2 a0 = make_float2(0.f, 0.f), a1 = a0, a2 = a0, a3 = a0;

    for (int e = beg; e < end; e += 8) {
        int4 q0 = *reinterpret_cast<const int4*>(&g_epair[e]);      // edges 0,1
        int4 q1 = *reinterpret_cast<const int4*>(&g_epair[e + 2]);  // edges 2,3
        int4 q2 = *reinterpret_cast<const int4*>(&g_epair[e + 4]);  // edges 4,5
        int4 q3 = *reinterpret_cast<const int4*>(&g_epair[e + 6]);  // edges 6,7

        float2 f0 = *reinterpret_cast<const float2*>(Hb + (unsigned)q0.x + loff);
        float2 f1 = *reinterpret_cast<const float2*>(Hb + (unsigned)q0.z + loff);
        float2 f2 = *reinterpret_cast<const float2*>(Hb + (unsigned)q1.x + loff);
        float2 f3 = *reinterpret_cast<const float2*>(Hb + (unsigned)q1.z + loff);
        float2 f4 = *reinterpret_cast<const float2*>(Hb + (unsigned)q2.x + loff);
        float2 f5 = *reinterpret_cast<const float2*>(Hb + (unsigned)q2.z + loff);
        float2 f6 = *reinterpret_cast<const float2*>(Hb + (unsigned)q3.x + loff);
        float2 f7 = *reinterpret_cast<const float2*>(Hb + (unsigned)q3.z + loff);

        float c0 = __int_as_float(q0.y), c1 = __int_as_float(q0.w);
        float c2 = __int_as_float(q1.y), c3 = __int_as_float(q1.w);
        float c4 = __int_as_float(q2.y), c5 = __int_as_float(q2.w);
        float c6 = __int_as_float(q3.y), c7 = __int_as_float(q3.w);

        a0.x = fmaf(c0, f0.x, a0.x); a0.y = fmaf(c0, f0.y, a0.y);
        a1.x = fmaf(c1, f1.x, a1.x); a1.y = fmaf(c1, f1.y, a1.y);
        a2.x = fmaf(c2, f2.x, a2.x); a2.y = fmaf(c2, f2.y, a2.y);
        a3.x = fmaf(c3, f3.x, a3.x); a3.y = fmaf(c3, f3.y, a3.y);
        a0.x = fmaf(c4, f4.x, a0.x); a0.y = fmaf(c4, f4.y, a0.y);
        a1.x = fmaf(c5, f5.x, a1.x); a1.y = fmaf(c5, f5.y, a1.y);
        a2.x = fmaf(c6, f6.x, a2.x); a2.y = fmaf(c6, f6.y, a2.y);
        a3.x = fmaf(c7, f7.x, a3.x); a3.y = fmaf(c7, f7.y, a3.y);
    }

    float dn = g_dis[n];
    float s2 = dn * dn;
    float2 hs = *reinterpret_cast<const float2*>(Hb + ((unsigned)n << 8) + loff);
    float2 bv = reinterpret_cast<const float2*>(b)[lane];

    float ox = (a0.x + a1.x) + (a2.x + a3.x) + hs.x * s2 + bv.x;
    float oy = (a0.y + a1.y) + (a2.y + a3.y) + hs.y * s2 + bv.y;
    if (do_relu) { ox = fmaxf(ox, 0.f); oy = fmaxf(oy, 0.f); }
    reinterpret_cast<float2*>(OUT)[((size_t)n << 5) + lane] = make_float2(ox, oy);
}

// ---------------------------------------------------------------------------
// Launch: gemm1 forked onto a second stream to overlap with the CSR build.
// ---------------------------------------------------------------------------
extern "C" void kernel_launch(void* const* d_in, const int* in_sizes, int n_in,
                              void* d_out, int out_size) {
    const float* x  = (const float*)d_in[0];
    const int*   ei = (const int*)d_in[1];
    const float* w  = (const float*)d_in[2];
    const float* W1 = (const float*)d_in[3];
    const float* b1 = (const float*)d_in[4];
    const float* W2 = (const float*)d_in[5];
    const float* b2 = (const float*)d_in[6];
    float* out = (float*)d_out;

    const int* src = ei;
    const int* dst = ei + EE;

    float* h_p;   cudaGetSymbolAddress((void**)&h_p,   g_h);
    float* agg_p; cudaGetSymbolAddress((void**)&agg_p, g_agg);

    const int T = 256;
    int bE4 = (EE / 4 + T - 1) / T;            // 1221
    int bG  = (NN + 127) / 128;                // 782
    int bW  = (NN * 32 + T - 1) / T;           // 12500 (1 warp/node)

    cudaStream_t s2;
    cudaStreamCreateWithFlags(&s2, cudaStreamNonBlocking);
    cudaEvent_t evFork, evJoin;
    cudaEventCreateWithFlags(&evFork, cudaEventDisableTiming);
    cudaEventCreateWithFlags(&evJoin, cudaEventDisableTiming);

    // Fork: gemm1 runs concurrent with the CSR build chain.
    cudaEventRecord(evFork, 0);
    cudaStreamWaitEvent(s2, evFork, 0);
    k_gemm<<<bG, T, 0, s2>>>(x, W1, h_p);

    // Build chain on stream 0.
    k_hist<<<bE4, T>>>(dst, w);
    k_scan1<<<NB, 256>>>();
    k_scan2<<<1, 512>>>();
    k_scan3<<<NB, 256>>>();
    k_reorder<<<bE4, T>>>(src, dst, w);

    // Join: gather1 needs both g_h (s2) and the CSR (stream 0).
    cudaEventRecord(evJoin, s2);
    cudaStreamWaitEvent(0, evJoin, 0);

    k_gather<<<bW, T>>>(h_p, agg_p, b1, 1);
    k_gemm<<<bG, T>>>(agg_p, W2, h_p);
    k_gather<<<bW, T>>>(h_p, out, b2, 0);
}

// round 14
// speedup vs baseline: 1.3002x; 1.0551x over previous
#include <cuda_runtime.h>
#include <cuda_bf16.h>
#include <cstdint>

#define NN 100000
#define EE 1250000
#define DD 64
#define NB ((NN + 255) / 256)   // 391 scan blocks
#define EPAD (EE + 8 * NN)      // padded edge capacity

// ---------------------------------------------------------------------------
// Scratch (__device__ globals; zero-initialized at load; self-restoring)
// ---------------------------------------------------------------------------
__device__ unsigned long long g_pack[NN];  // [63:48] count, [47:0] w*2^40 (cleared by scan1)
__device__ float g_dis[NN];                // deg^{-1/2}
__device__ int   g_fill[NN];               // reorder cursor (= global rowstart after scan3)
__device__ int   g_rowstart[NN];           // padded start (global after scan3)
__device__ int   g_rowend[NN];             // padded end (global after scan3)
__device__ int   g_bsum[NB];               // padded block totals
__device__ int   g_bsumx[NB];              // exclusive block offsets
__device__ __align__(16) int2 g_epair[EPAD]; // (src*256, coef-bits); pad slots stay (0,0)
__device__ float g_h[NN * DD];             // gemm output buffer
__device__ float g_agg[NN * DD];           // gather output buffer

// ---------------------------------------------------------------------------
// Histogram: ONE packed u64 atomic per edge (count<<48 | w*2^40).
// ---------------------------------------------------------------------------
__global__ void k_hist(const int* __restrict__ dst, const float* __restrict__ w) {
    int t = blockIdx.x * blockDim.x + threadIdx.x;
    int e = t * 4;
    const float FP = 1099511627776.0f;  // 2^40
    if (e + 4 <= EE) {
        int4 d = *reinterpret_cast<const int4*>(dst + e);
        float4 wv = *reinterpret_cast<const float4*>(w + e);
        atomicAdd(&g_pack[d.x], (1ULL << 48) | (unsigned long long)(wv.x * FP));
        atomicAdd(&g_pack[d.y], (1ULL << 48) | (unsigned long long)(wv.y * FP));
        atomicAdd(&g_pack[d.z], (1ULL << 48) | (unsigned long long)(wv.z * FP));
        atomicAdd(&g_pack[d.w], (1ULL << 48) | (unsigned long long)(wv.w * FP));
    } else {
        for (; e < EE; e++)
            atomicAdd(&g_pack[dst[e]], (1ULL << 48) | (unsigned long long)(w[e] * FP));
    }
}

// ---------------------------------------------------------------------------
// scan1: read+clear pack, compute dis, scan PADDED counts.
// ---------------------------------------------------------------------------
__global__ void k_scan1() {
    __shared__ int sh[256];
    int t = threadIdx.x;
    int i = blockIdx.x * 256 + t;
    int cntp = 0;
    if (i < NN) {
        unsigned long long p = g_pack[i];
        g_pack[i] = 0ULL;                              // restore for next run
        int cnt = (int)(p >> 48);
        float deg = (float)(p & ((1ULL << 48) - 1ULL)) * (1.0f / 1099511627776.0f);
        g_dis[i] = rsqrtf(deg + 1.0f);
        cntp = (cnt + 7) & ~7;                         // pad to multiple of 8
    }
    sh[t] = cntp;
    __syncthreads();
    for (int off = 1; off < 256; off <<= 1) {
        int u = (t >= off) ? sh[t - off] : 0;
        __syncthreads();
        sh[t] += u;
        __syncthreads();
    }
    if (i < NN) {
        g_rowstart[i] = sh[t] - cntp;                  // local exclusive (mult of 8)
        g_rowend[i]   = sh[t];                         // local inclusive padded
    }
    if (t == 255) g_bsum[blockIdx.x] = sh[255];
}

// scan2: exclusive scan of 391 padded block totals -> g_bsumx
__global__ void k_scan2() {
    __shared__ int sh[512];
    int t = threadIdx.x;
    int v = (t < NB) ? g_bsum[t] : 0;
    sh[t] = v;
    __syncthreads();
    for (int off = 1; off < 512; off <<= 1) {
        int u = (t >= off) ? sh[t - off] : 0;
        __syncthreads();
        sh[t] += u;
        __syncthreads();
    }
    if (t < NB) g_bsumx[t] = sh[t] - v;
}

// scan3: globalize rowstart/rowend; prime fill cursor with global rowstart.
__global__ void k_scan3() {
    int i = blockIdx.x * 256 + threadIdx.x;
    if (i < NN) {
        int off = g_bsumx[i >> 8];
        int rs = g_rowstart[i] + off;
        g_rowstart[i] = rs;
        g_rowend[i]  += off;
        g_fill[i] = rs;                                // cursor = global start
    }
}

// ---------------------------------------------------------------------------
// Reorder: pos = atomicAdd(fill[d], 1). ONE atomic, no extra loads.
// ---------------------------------------------------------------------------
__global__ void k_reorder(const int* __restrict__ src, const int* __restrict__ dst,
                          const float* __restrict__ w) {
    int t = blockIdx.x * blockDim.x + threadIdx.x;
    int e = t * 4;
    if (e + 4 <= EE) {
        int4 s = *reinterpret_cast<const int4*>(src + e);
        int4 d = *reinterpret_cast<const int4*>(dst + e);
        float4 wv = *reinterpret_cast<const float4*>(w + e);
        float c0 = g_dis[s.x] * wv.x * g_dis[d.x];
        float c1 = g_dis[s.y] * wv.y * g_dis[d.y];
        float c2 = g_dis[s.z] * wv.z * g_dis[d.z];
        float c3 = g_dis[s.w] * wv.w * g_dis[d.w];
        int p0 = atomicAdd(&g_fill[d.x], 1);
        int p1 = atomicAdd(&g_fill[d.y], 1);
        int p2 = atomicAdd(&g_fill[d.z], 1);
        int p3 = atomicAdd(&g_fill[d.w], 1);
        g_epair[p0] = make_int2(s.x << 8, __float_as_int(c0));
        g_epair[p1] = make_int2(s.y << 8, __float_as_int(c1));
        g_epair[p2] = make_int2(s.z << 8, __float_as_int(c2));
        g_epair[p3] = make_int2(s.w << 8, __float_as_int(c3));
    } else {
        for (; e < EE; e++) {
            int sv = src[e];
            int d = dst[e];
            float c = g_dis[sv] * w[e] * g_dis[d];
            int pos = atomicAdd(&g_fill[d], 1);
            g_epair[pos] = make_int2(sv << 8, __float_as_int(c));
        }
    }
}

// ---------------------------------------------------------------------------
// Register-blocked GEMM (R7-proven, 41us): H[n][o] = sum_k X[n][k]*W[o][k]
// ---------------------------------------------------------------------------
__global__ void __launch_bounds__(256) k_gemm(const float* __restrict__ X,
                                              const float* __restrict__ W,
                                              float* __restrict__ H) {
    __shared__ float Xs[128][65];
    __shared__ float Ws[DD][DD];      // Ws[k][o] = W[o][k]

    int tid = threadIdx.x;
    int lane = tid & 31;
    int grp  = tid >> 5;
    int row0 = blockIdx.x * 128;

    for (int idx = tid; idx < (DD * DD) / 4; idx += 256) {
        int o = idx >> 4;
        int k4 = (idx & 15) * 4;
        float4 v = *reinterpret_cast<const float4*>(W + o * DD + k4);
        Ws[k4 + 0][o] = v.x;
        Ws[k4 + 1][o] = v.y;
        Ws[k4 + 2][o] = v.z;
        Ws[k4 + 3][o] = v.w;
    }
    for (int idx = tid; idx < (128 * DD) / 4; idx += 256) {
        int r = idx >> 4;
        int k4 = (idx & 15) * 4;
        int row = row0 + r;
        float4 v = (row < NN) ? *reinterpret_cast<const float4*>(X + (size_t)row * DD + k4)
                              : make_float4(0.f, 0.f, 0.f, 0.f);
        Xs[r][k4 + 0] = v.x;
        Xs[r][k4 + 1] = v.y;
        Xs[r][k4 + 2] = v.z;
        Xs[r][k4 + 3] = v.w;
    }
    __syncthreads();

    int c0 = grp * 8;
    float acc[4][8];
#pragma unroll
    for (int i = 0; i < 4; i++)
#pragma unroll
        for (int j = 0; j < 8; j++) acc[i][j] = 0.0f;

#pragma unroll 4
    for (int k = 0; k < DD; k++) {
        float xv0 = Xs[lane      ][k];
        float xv1 = Xs[lane + 32 ][k];
        float xv2 = Xs[lane + 64 ][k];
        float xv3 = Xs[lane + 96 ][k];
        float4 w0 = *reinterpret_cast<const float4*>(&Ws[k][c0]);
        float4 w1 = *reinterpret_cast<const float4*>(&Ws[k][c0 + 4]);
        float wv[8] = {w0.x, w0.y, w0.z, w0.w, w1.x, w1.y, w1.z, w1.w};
#pragma unroll
        for (int j = 0; j < 8; j++) {
            acc[0][j] = fmaf(xv0, wv[j], acc[0][j]);
            acc[1][j] = fmaf(xv1, wv[j], acc[1][j]);
            acc[2][j] = fmaf(xv2, wv[j], acc[2][j]);
            acc[3][j] = fmaf(xv3, wv[j], acc[3][j]);
        }
    }

#pragma unroll
    for (int i = 0; i < 4; i++) {
        int row = row0 + lane + i * 32;
        if (row < NN) {
            float* hp = H + (size_t)row * DD + c0;
            *reinterpret_cast<float4*>(hp)     = make_float4(acc[i][0], acc[i][1], acc[i][2], acc[i][3]);
            *reinterpret_cast<float4*>(hp + 4) = make_float4(acc[i][4], acc[i][5], acc[i][6], acc[i][7]);
        }
    }
}

// ---------------------------------------------------------------------------
// CSR gather, 1 warp/node, float2/lane. Padded rows: no predication, no tail.
// ---------------------------------------------------------------------------
__global__ void __launch_bounds__(256) k_gather(const float* __restrict__ H,
                                                float* __restrict__ OUT,
                                                const float* __restrict__ b,
                                                int do_relu) {
    int n = (blockIdx.x * blockDim.x + threadIdx.x) >> 5;
    if (n >= NN) return;
    int lane = threadIdx.x & 31;
    const char* __restrict__ Hb = reinterpret_cast<const char*>(H);
    unsigned loff = (unsigned)lane * 8u;

    int beg = g_rowstart[n];
    int end = g_rowend[n];

    float2 a0 = make_float2(0.f, 0.f), a1 = a0, a2 = a0, a3 = a0;

    for (int e = beg; e < end; e += 8) {
        int4 q0 = *reinterpret_cast<const int4*>(&g_epair[e]);      // edges 0,1
        int4 q1 = *reinterpret_cast<const int4*>(&g_epair[e + 2]);  // edges 2,3
        int4 q2 = *reinterpret_cast<const int4*>(&g_epair[e + 4]);  // edges 4,5
        int4 q3 = *reinterpret_cast<const int4*>(&g_epair[e + 6]);  // edges 6,7

        float2 f0 = *reinterpret_cast<const float2*>(Hb + (unsigned)q0.x + loff);
        float2 f1 = *reinterpret_cast<const float2*>(Hb + (unsigned)q0.z + loff);
        float2 f2 = *reinterpret_cast<const float2*>(Hb + (unsigned)q1.x + loff);
        float2 f3 = *reinterpret_cast<const float2*>(Hb + (unsigned)q1.z + loff);
        float2 f4 = *reinterpret_cast<const float2*>(Hb + (unsigned)q2.x + loff);
        float2 f5 = *reinterpret_cast<const float2*>(Hb + (unsigned)q2.z + loff);
        float2 f6 = *reinterpret_cast<const float2*>(Hb + (unsigned)q3.x + loff);
        float2 f7 = *reinterpret_cast<const float2*>(Hb + (unsigned)q3.z + loff);

        float c0 = __int_as_float(q0.y), c1 = __int_as_float(q0.w);
        float c2 = __int_as_float(q1.y), c3 = __int_as_float(q1.w);
        float c4 = __int_as_float(q2.y), c5 = __int_as_float(q2.w);
        float c6 = __int_as_float(q3.y), c7 = __int_as_float(q3.w);

        a0.x = fmaf(c0, f0.x, a0.x); a0.y = fmaf(c0, f0.y, a0.y);
        a1.x = fmaf(c1, f1.x, a1.x); a1.y = fmaf(c1, f1.y, a1.y);
        a2.x = fmaf(c2, f2.x, a2.x); a2.y = fmaf(c2, f2.y, a2.y);
        a3.x = fmaf(c3, f3.x, a3.x); a3.y = fmaf(c3, f3.y, a3.y);
        a0.x = fmaf(c4, f4.x, a0.x); a0.y = fmaf(c4, f4.y, a0.y);
        a1.x = fmaf(c5, f5.x, a1.x); a1.y = fmaf(c5, f5.y, a1.y);
        a2.x = fmaf(c6, f6.x, a2.x); a2.y = fmaf(c6, f6.y, a2.y);
        a3.x = fmaf(c7, f7.x, a3.x); a3.y = fmaf(c7, f7.y, a3.y);
    }

    float dn = g_dis[n];
    float s2 = dn * dn;
    float2 hs = *reinterpret_cast<const float2*>(Hb + ((unsigned)n << 8) + loff);
    float2 bv = reinterpret_cast<const float2*>(b)[lane];

    float ox = (a0.x + a1.x) + (a2.x + a3.x) + hs.x * s2 + bv.x;
    float oy = (a0.y + a1.y) + (a2.y + a3.y) + hs.y * s2 + bv.y;
    if (do_relu) { ox = fmaxf(ox, 0.f); oy = fmaxf(oy, 0.f); }
    reinterpret_cast<float2*>(OUT)[((size_t)n << 5) + lane] = make_float2(ox, oy);
}

// ---------------------------------------------------------------------------
// Launch: gemm1 forked onto a second stream to overlap with the CSR build.
// ---------------------------------------------------------------------------
extern "C" void kernel_launch(void* const* d_in, const int* in_sizes, int n_in,
                              void* d_out, int out_size) {
    const float* x  = (const float*)d_in[0];
    const int*   ei = (const int*)d_in[1];
    const float* w  = (const float*)d_in[2];
    const float* W1 = (const float*)d_in[3];
    const float* b1 = (const float*)d_in[4];
    const float* W2 = (const float*)d_in[5];
    const float* b2 = (const float*)d_in[6];
    float* out = (float*)d_out;

    const int* src = ei;
    const int* dst = ei + EE;

    float* h_p;   cudaGetSymbolAddress((void**)&h_p,   g_h);
    float* agg_p; cudaGetSymbolAddress((void**)&agg_p, g_agg);

    const int T = 256;
    int bE4 = (EE / 4 + T - 1) / T;            // 1221
    int bG  = (NN + 127) / 128;                // 782
    int bW  = (NN * 32 + T - 1) / T;           // 12500 (1 warp/node)

    cudaStream_t s2;
    cudaStreamCreateWithFlags(&s2, cudaStreamNonBlocking);
    cudaEvent_t evFork, evJoin;
    cudaEventCreateWithFlags(&evFork, cudaEventDisableTiming);
    cudaEventCreateWithFlags(&evJoin, cudaEventDisableTiming);

    // Fork: gemm1 runs concurrent with the CSR build chain.
    cudaEventRecord(evFork, 0);
    cudaStreamWaitEvent(s2, evFork, 0);
    k_gemm<<<bG, T, 0, s2>>>(x, W1, h_p);

    // Build chain on stream 0.
    k_hist<<<bE4, T>>>(dst, w);
    k_scan1<<<NB, 256>>>();
    k_scan2<<<1, 512>>>();
    k_scan3<<<NB, 256>>>();
    k_reorder<<<bE4, T>>>(src, dst, w);

    // Join: gather1 needs both g_h (s2) and the CSR (stream 0).
    cudaEventRecord(evJoin, s2);
    cudaStreamWaitEvent(0, evJoin, 0);

    k_gather<<<bW, T>>>(h_p, agg_p, b1, 1);
    k_gemm<<<bG, T>>>(agg_p, W2, h_p);
    k_gather<<<bW, T>>>(h_p, out, b2, 0);
}

// round 15
// speedup vs baseline: 1.3797x; 1.0612x over previous
#include <cuda_runtime.h>
#include <cuda_bf16.h>
#include <cstdint>

#define NN 100000
#define EE 1250000
#define DD 64
#define NB ((NN + 255) / 256)   // 391 scan blocks
#define EPAD (EE + 8 * NN)      // padded edge capacity

// ---------------------------------------------------------------------------
// Scratch (__device__ globals; zero-initialized at load; self-restoring)
// ---------------------------------------------------------------------------
__device__ unsigned long long g_pack[NN];  // [63:48] count, [47:0] w*2^40 (cleared by scan1)
__device__ float g_dis[NN];                // deg^{-1/2}
__device__ int   g_fill[NN];               // reorder cursor (= global rowstart after scan3)
__device__ int   g_rowstart[NN];           // padded start (global after scan3)
__device__ int   g_rowend[NN];             // padded end (global after scan3)
__device__ int   g_bsum[NB];               // padded block totals
__device__ __align__(16) int2 g_epair[EPAD]; // (src*256, coef-bits); pad slots stay (0,0)
__device__ float g_h[NN * DD];             // gemm output buffer
__device__ float g_agg[NN * DD];           // gather output buffer

// ---------------------------------------------------------------------------
// Histogram: ONE packed u64 atomic per edge (count<<48 | w*2^40).
// ---------------------------------------------------------------------------
__global__ void k_hist(const int* __restrict__ dst, const float* __restrict__ w) {
    int t = blockIdx.x * blockDim.x + threadIdx.x;
    int e = t * 4;
    const float FP = 1099511627776.0f;  // 2^40
    if (e + 4 <= EE) {
        int4 d = *reinterpret_cast<const int4*>(dst + e);
        float4 wv = *reinterpret_cast<const float4*>(w + e);
        atomicAdd(&g_pack[d.x], (1ULL << 48) | (unsigned long long)(wv.x * FP));
        atomicAdd(&g_pack[d.y], (1ULL << 48) | (unsigned long long)(wv.y * FP));
        atomicAdd(&g_pack[d.z], (1ULL << 48) | (unsigned long long)(wv.z * FP));
        atomicAdd(&g_pack[d.w], (1ULL << 48) | (unsigned long long)(wv.w * FP));
    } else {
        for (; e < EE; e++)
            atomicAdd(&g_pack[dst[e]], (1ULL << 48) | (unsigned long long)(w[e] * FP));
    }
}

// ---------------------------------------------------------------------------
// scan1: read+clear pack, compute dis, scan PADDED counts (block-local).
// ---------------------------------------------------------------------------
__global__ void k_scan1() {
    __shared__ int sh[256];
    int t = threadIdx.x;
    int i = blockIdx.x * 256 + t;
    int cntp = 0;
    if (i < NN) {
        unsigned long long p = g_pack[i];
        g_pack[i] = 0ULL;                              // restore for next run
        int cnt = (int)(p >> 48);
        float deg = (float)(p & ((1ULL << 48) - 1ULL)) * (1.0f / 1099511627776.0f);
        g_dis[i] = rsqrtf(deg + 1.0f);
        cntp = (cnt + 7) & ~7;                         // pad to multiple of 8
    }
    sh[t] = cntp;
    __syncthreads();
    for (int off = 1; off < 256; off <<= 1) {
        int u = (t >= off) ? sh[t - off] : 0;
        __syncthreads();
        sh[t] += u;
        __syncthreads();
    }
    if (i < NN) {
        g_rowstart[i] = sh[t] - cntp;                  // local exclusive (mult of 8)
        g_rowend[i]   = sh[t];                         // local inclusive padded
    }
    if (t == 255) g_bsum[blockIdx.x] = sh[255];
}

// scan3 (fused scan2): each block reduces its own prefix of g_bsum,
// globalizes rowstart/rowend, primes the fill cursor.
__global__ void k_scan3() {
    __shared__ int sh[256];
    int t = threadIdx.x;
    int bid = blockIdx.x;
    int s = 0;
    for (int j = t; j < bid; j += 256) s += g_bsum[j];
    sh[t] = s;
    __syncthreads();
    for (int off = 128; off > 0; off >>= 1) {
        if (t < off) sh[t] += sh[t + off];
        __syncthreads();
    }
    int off = sh[0];
    int i = bid * 256 + t;
    if (i < NN) {
        int rs = g_rowstart[i] + off;
        g_rowstart[i] = rs;
        g_rowend[i]  += off;
        g_fill[i] = rs;                                // cursor = global start
    }
}

// ---------------------------------------------------------------------------
// Reorder: pos = atomicAdd(fill[d], 1). ONE atomic, no extra loads.
// ---------------------------------------------------------------------------
__global__ void k_reorder(const int* __restrict__ src, const int* __restrict__ dst,
                          const float* __restrict__ w) {
    int t = blockIdx.x * blockDim.x + threadIdx.x;
    int e = t * 4;
    if (e + 4 <= EE) {
        int4 s = *reinterpret_cast<const int4*>(src + e);
        int4 d = *reinterpret_cast<const int4*>(dst + e);
        float4 wv = *reinterpret_cast<const float4*>(w + e);
        float c0 = g_dis[s.x] * wv.x * g_dis[d.x];
        float c1 = g_dis[s.y] * wv.y * g_dis[d.y];
        float c2 = g_dis[s.z] * wv.z * g_dis[d.z];
        float c3 = g_dis[s.w] * wv.w * g_dis[d.w];
        int p0 = atomicAdd(&g_fill[d.x], 1);
        int p1 = atomicAdd(&g_fill[d.y], 1);
        int p2 = atomicAdd(&g_fill[d.z], 1);
        int p3 = atomicAdd(&g_fill[d.w], 1);
        g_epair[p0] = make_int2(s.x << 8, __float_as_int(c0));
        g_epair[p1] = make_int2(s.y << 8, __float_as_int(c1));
        g_epair[p2] = make_int2(s.z << 8, __float_as_int(c2));
        g_epair[p3] = make_int2(s.w << 8, __float_as_int(c3));
    } else {
        for (; e < EE; e++) {
            int sv = src[e];
            int d = dst[e];
            float c = g_dis[sv] * w[e] * g_dis[d];
            int pos = atomicAdd(&g_fill[d], 1);
            g_epair[pos] = make_int2(sv << 8, __float_as_int(c));
        }
    }
}

// ---------------------------------------------------------------------------
// Register-blocked GEMM (R7-proven, 41us): H[n][o] = sum_k X[n][k]*W[o][k]
// ---------------------------------------------------------------------------
__global__ void __launch_bounds__(256) k_gemm(const float* __restrict__ X,
                                              const float* __restrict__ W,
                                              float* __restrict__ H) {
    __shared__ float Xs[128][65];
    __shared__ float Ws[DD][DD];      // Ws[k][o] = W[o][k]

    int tid = threadIdx.x;
    int lane = tid & 31;
    int grp  = tid >> 5;
    int row0 = blockIdx.x * 128;

    for (int idx = tid; idx < (DD * DD) / 4; idx += 256) {
        int o = idx >> 4;
        int k4 = (idx & 15) * 4;
        float4 v = *reinterpret_cast<const float4*>(W + o * DD + k4);
        Ws[k4 + 0][o] = v.x;
        Ws[k4 + 1][o] = v.y;
        Ws[k4 + 2][o] = v.z;
        Ws[k4 + 3][o] = v.w;
    }
    for (int idx = tid; idx < (128 * DD) / 4; idx += 256) {
        int r = idx >> 4;
        int k4 = (idx & 15) * 4;
        int row = row0 + r;
        float4 v = (row < NN) ? *reinterpret_cast<const float4*>(X + (size_t)row * DD + k4)
                              : make_float4(0.f, 0.f, 0.f, 0.f);
        Xs[r][k4 + 0] = v.x;
        Xs[r][k4 + 1] = v.y;
        Xs[r][k4 + 2] = v.z;
        Xs[r][k4 + 3] = v.w;
    }
    __syncthreads();

    int c0 = grp * 8;
    float acc[4][8];
#pragma unroll
    for (int i = 0; i < 4; i++)
#pragma unroll
        for (int j = 0; j < 8; j++) acc[i][j] = 0.0f;

#pragma unroll 4
    for (int k = 0; k < DD; k++) {
        float xv0 = Xs[lane      ][k];
        float xv1 = Xs[lane + 32 ][k];
        float xv2 = Xs[lane + 64 ][k];
        float xv3 = Xs[lane + 96 ][k];
        float4 w0 = *reinterpret_cast<const float4*>(&Ws[k][c0]);
        float4 w1 = *reinterpret_cast<const float4*>(&Ws[k][c0 + 4]);
        float wv[8] = {w0.x, w0.y, w0.z, w0.w, w1.x, w1.y, w1.z, w1.w};
#pragma unroll
        for (int j = 0; j < 8; j++) {
            acc[0][j] = fmaf(xv0, wv[j], acc[0][j]);
            acc[1][j] = fmaf(xv1, wv[j], acc[1][j]);
            acc[2][j] = fmaf(xv2, wv[j], acc[2][j]);
            acc[3][j] = fmaf(xv3, wv[j], acc[3][j]);
        }
    }

#pragma unroll
    for (int i = 0; i < 4; i++) {
        int row = row0 + lane + i * 32;
        if (row < NN) {
            float* hp = H + (size_t)row * DD + c0;
            *reinterpret_cast<float4*>(hp)     = make_float4(acc[i][0], acc[i][1], acc[i][2], acc[i][3]);
            *reinterpret_cast<float4*>(hp + 4) = make_float4(acc[i][4], acc[i][5], acc[i][6], acc[i][7]);
        }
    }
}

// ---------------------------------------------------------------------------
// CSR gather, 1 warp/node. Lane split: half = lane>>4 picks even/odd edge,
// q = lane&15 picks the float4 chunk. One warp LDG.128 covers 2 edge-rows.
// Padded rows (mult of 8): no predication, no tail.
// ---------------------------------------------------------------------------
__global__ void __launch_bounds__(256) k_gather(const float* __restrict__ H,
                                                float* __restrict__ OUT,
                                                const float* __restrict__ b,
                                                int do_relu) {
    int n = (blockIdx.x * blockDim.x + threadIdx.x) >> 5;
    if (n >= NN) return;
    int lane = threadIdx.x & 31;
    int half = lane >> 4;             // 0: even edge of pair, 1: odd edge
    unsigned qoff = (unsigned)(lane & 15) * 16u;
    const char* __restrict__ Hb = reinterpret_cast<const char*>(H);

    int beg = g_rowstart[n];
    int end = g_rowend[n];

    float4 a0 = make_float4(0.f, 0.f, 0.f, 0.f);
    float4 a1 = a0;

    for (int e = beg; e < end; e += 8) {
        int4 p0 = *reinterpret_cast<const int4*>(&g_epair[e]);      // edges 0,1
        int4 p1 = *reinterpret_cast<const int4*>(&g_epair[e + 2]);  // edges 2,3
        int4 p2 = *reinterpret_cast<const int4*>(&g_epair[e + 4]);  // edges 4,5
        int4 p3 = *reinterpret_cast<const int4*>(&g_epair[e + 6]);  // edges 6,7

        unsigned o0 = (unsigned)(half ? p0.z : p0.x);
        unsigned o1 = (unsigned)(half ? p1.z : p1.x);
        unsigned o2 = (unsigned)(half ? p2.z : p2.x);
        unsigned o3 = (unsigned)(half ? p3.z : p3.x);

        float4 f0 = *reinterpret_cast<const float4*>(Hb + o0 + qoff);
        float4 f1 = *reinterpret_cast<const float4*>(Hb + o1 + qoff);
        float4 f2 = *reinterpret_cast<const float4*>(Hb + o2 + qoff);
        float4 f3 = *reinterpret_cast<const float4*>(Hb + o3 + qoff);

        float c0 = __int_as_float(half ? p0.w : p0.y);
        float c1 = __int_as_float(half ? p1.w : p1.y);
        float c2 = __int_as_float(half ? p2.w : p2.y);
        float c3 = __int_as_float(half ? p3.w : p3.y);

        a0.x = fmaf(c0, f0.x, a0.x); a0.y = fmaf(c0, f0.y, a0.y);
        a0.z = fmaf(c0, f0.z, a0.z); a0.w = fmaf(c0, f0.w, a0.w);
        a1.x = fmaf(c1, f1.x, a1.x); a1.y = fmaf(c1, f1.y, a1.y);
        a1.z = fmaf(c1, f1.z, a1.z); a1.w = fmaf(c1, f1.w, a1.w);
        a0.x = fmaf(c2, f2.x, a0.x); a0.y = fmaf(c2, f2.y, a0.y);
        a0.z = fmaf(c2, f2.z, a0.z); a0.w = fmaf(c2, f2.w, a0.w);
        a1.x = fmaf(c3, f3.x, a1.x); a1.y = fmaf(c3, f3.y, a1.y);
        a1.z = fmaf(c3, f3.z, a1.z); a1.w = fmaf(c3, f3.w, a1.w);
    }

    // combine the two edge-parity halves
    float4 a;
    a.x = a0.x + a1.x; a.y = a0.y + a1.y;
    a.z = a0.z + a1.z; a.w = a0.w + a1.w;
    a.x += __shfl_xor_sync(0xffffffffu, a.x, 16);
    a.y += __shfl_xor_sync(0xffffffffu, a.y, 16);
    a.z += __shfl_xor_sync(0xffffffffu, a.z, 16);
    a.w += __shfl_xor_sync(0xffffffffu, a.w, 16);

    float dn = g_dis[n];
    float s2 = dn * dn;
    float4 hs = *reinterpret_cast<const float4*>(Hb + ((unsigned)n << 8) + qoff);
    float4 bv = reinterpret_cast<const float4*>(b)[lane & 15];

    float4 r;
    r.x = a.x + hs.x * s2 + bv.x;
    r.y = a.y + hs.y * s2 + bv.y;
    r.z = a.z + hs.z * s2 + bv.z;
    r.w = a.w + hs.w * s2 + bv.w;
    if (do_relu) {
        r.x = fmaxf(r.x, 0.f); r.y = fmaxf(r.y, 0.f);
        r.z = fmaxf(r.z, 0.f); r.w = fmaxf(r.w, 0.f);
    }
    if (half == 0)
        reinterpret_cast<float4*>(OUT)[((size_t)n << 4) + (lane & 15)] = r;
}

// ---------------------------------------------------------------------------
// Launch: gemm1 forked onto a second stream to overlap with the CSR build.
// ---------------------------------------------------------------------------
extern "C" void kernel_launch(void* const* d_in, const int* in_sizes, int n_in,
                              void* d_out, int out_size) {
    const float* x  = (const float*)d_in[0];
    const int*   ei = (const int*)d_in[1];
    const float* w  = (const float*)d_in[2];
    const float* W1 = (const float*)d_in[3];
    const float* b1 = (const float*)d_in[4];
    const float* W2 = (const float*)d_in[5];
    const float* b2 = (const float*)d_in[6];
    float* out = (float*)d_out;

    const int* src = ei;
    const int* dst = ei + EE;

    float* h_p;   cudaGetSymbolAddress((void**)&h_p,   g_h);
    float* agg_p; cudaGetSymbolAddress((void**)&agg_p, g_agg);

    const int T = 256;
    int bE4 = (EE / 4 + T - 1) / T;            // 1221
    int bG  = (NN + 127) / 128;                // 782
    int bW  = (NN * 32 + T - 1) / T;           // 12500 (1 warp/node)

    cudaStream_t s2;
    cudaStreamCreateWithFlags(&s2, cudaStreamNonBlocking);
    cudaEvent_t evFork, evJoin;
    cudaEventCreateWithFlags(&evFork, cudaEventDisableTiming);
    cudaEventCreateWithFlags(&evJoin, cudaEventDisableTiming);

    // Fork: gemm1 runs concurrent with the CSR build chain.
    cudaEventRecord(evFork, 0);
    cudaStreamWaitEvent(s2, evFork, 0);
    k_gemm<<<bG, T, 0, s2>>>(x, W1, h_p);

    // Build chain on stream 0.
    k_hist<<<bE4, T>>>(dst, w);
    k_scan1<<<NB, 256>>>();
    k_scan3<<<NB, 256>>>();
    k_reorder<<<bE4, T>>>(src, dst, w);

    // Join: gather1 needs both g_h (s2) and the CSR (stream 0).
    cudaEventRecord(evJoin, s2);
    cudaStreamWaitEvent(0, evJoin, 0);

    k_gather<<<bW, T>>>(h_p, agg_p, b1, 1);
    k_gemm<<<bG, T>>>(agg_p, W2, h_p);
    k_gather<<<bW, T>>>(h_p, out, b2, 0);
}